// round 10
// baseline (speedup 1.0000x reference)
#include <cuda_runtime.h>
#include <cuda_bf16.h>

// Problem shapes (fixed by reference setup_inputs)
#define B    4
#define CIN  512
#define OUT  256
#define NN   4096

#define GRID 148          // one block per SM -> whole grid resident in wave 1
#define TPB  1024         // 32 warps; launch_bounds caps regs at 64 (exact RF fit)

#define NROWS   (B * CIN)         // 2048 input rows
#define NHALF   (2 * NROWS)       // 4096 half-row items   (phase 1)
#define NQUART  (4 * B * OUT)     // 4096 quarter-row items (phase 2)

// Scratch + barrier state (zero-init; sense-reversal is replay-safe)
__device__ float    g_Xp[2][NROWS];   // half-row partial sums; X = g_Xp[0]+g_Xp[1]
__device__ unsigned g_count = 0;
__device__ unsigned g_sense = 0;

__global__ void __launch_bounds__(TPB, 1)
k_all(const float* __restrict__ x, const float* __restrict__ W1,
      float* __restrict__ out) {
    const int t    = threadIdx.x;
    const int w    = t >> 5;           // 0..31
    const int lane = t & 31;
    const int blk  = blockIdx.x;       // 0..147

    // Capture sense before any work (no block can flip it until all arrive).
    const unsigned sense0 = *(volatile unsigned*)&g_sense;

    // ---------------- phase 1: one half-row (8 KB) per warp ----------------
    const int item1 = w * GRID + blk;        // 0..4735; 4096 active
    if (item1 < NHALF) {
        const int row  = item1 >> 1;
        const int half = item1 & 1;
        const float4* __restrict__ p = reinterpret_cast<const float4*>(x)
                                     + (size_t)row * (NN / 4) + half * 512;
        float s = 0.f;
        #pragma unroll
        for (int g = 0; g < 2; g++) {        // 2 groups of 8 in-flight loads
            float4 v[8];
            #pragma unroll
            for (int i = 0; i < 8; i++) v[i] = p[lane + (g * 8 + i) * 32];
            #pragma unroll
            for (int i = 0; i < 8; i++)
                s += (v[i].x + v[i].y) + (v[i].z + v[i].w);
        }
        #pragma unroll
        for (int off = 16; off > 0; off >>= 1)
            s += __shfl_down_sync(0xffffffffu, s, off);
        if (lane == 0) g_Xp[half][row] = s;
    }
    __threadfence();                         // publish partials before arrival
    __syncthreads();

    // ---------------- 148-way sense barrier with backoff ----------------
    if (t == 0) {
        const unsigned prev = atomicAdd(&g_count, 1u);
        if (prev == GRID - 1) {
            g_count = 0;                     // reset for next graph replay
            __threadfence();
            *(volatile unsigned*)&g_sense = sense0 ^ 1u;
        } else {
            while (*(volatile unsigned*)&g_sense == sense0)
                __nanosleep(64);             // keep pollers off the LTS
        }
        __threadfence();                     // acquire peers' writes
    }
    __syncthreads();

    // ---------------- phase 2: one quarter output row per warp --------------
    const int item2 = w * GRID + blk;        // 0..4735; 4096 active
    if (item2 < NQUART) {
        const int ro  = item2 >> 2;          // output row 0..1023
        const int qtr = item2 & 3;
        const int b   = ro >> 8;             // OUT = 256
        const int o   = ro & 255;

        const float4* __restrict__ wr =
            reinterpret_cast<const float4*>(W1) + (size_t)o * (CIN / 4);
        const float4* __restrict__ x0 =
            reinterpret_cast<const float4*>(g_Xp[0]) + (size_t)b * (CIN / 4);
        const float4* __restrict__ x1 =
            reinterpret_cast<const float4*>(g_Xp[1]) + (size_t)b * (CIN / 4);

        float s = 0.f;
        #pragma unroll
        for (int k = 0; k < 4; k++) {
            const int idx = lane + k * 32;
            const float4 a  = wr[idx];
            const float4 u0 = __ldcg(x0 + idx);
            const float4 u1 = __ldcg(x1 + idx);
            const float4 xv = make_float4(u0.x + u1.x, u0.y + u1.y,
                                          u0.z + u1.z, u0.w + u1.w);
            s = fmaf(a.x, xv.x, fmaf(a.y, xv.y,
                fmaf(a.z, xv.z, fmaf(a.w, xv.w, s))));
        }
        #pragma unroll
        for (int off = 16; off > 0; off >>= 1)   // butterfly: all lanes get sum
            s += __shfl_xor_sync(0xffffffffu, s, off);

        const float  e  = (s > 0.f) ? s : expm1f(s);   // elu, alpha=1
        const float4 v4 = make_float4(e, e, e, e);

        float4* __restrict__ q = reinterpret_cast<float4*>(out)
                               + (size_t)ro * (NN / 4) + qtr * 256;
        #pragma unroll
        for (int i = 0; i < 8; i++)              // 256 float4 / 32 lanes
            q[lane + i * 32] = v4;
    }
}

extern "C" void kernel_launch(void* const* d_in, const int* in_sizes, int n_in,
                              void* d_out, int out_size) {
    const float* x  = (const float*)d_in[0];   // [B, CIN, 1, NN]
    const float* W1 = (const float*)d_in[1];   // [OUT, CIN]
    // d_in[2] = w2, d_in[3] = bias_mat: unused (softmax over size-1 axis == 1)
    float* out = (float*)d_out;                // [B, OUT, 1, NN]

    k_all<<<GRID, TPB>>>(x, W1, out);
}

// round 11
// speedup vs baseline: 1.2202x; 1.2202x over previous
#include <cuda_runtime.h>
#include <cuda_bf16.h>

// Problem shapes (fixed by reference setup_inputs)
#define B    4
#define CIN  512
#define OUT  256
#define NN   4096

// Scratch (no cudaMalloc allowed); fully overwritten every run
__device__ float g_X[B * CIN];   // X[b,c] = sum_n x[b,c,n]

// ---------------------------------------------------------------------------
// Kernel 1 (half-range): reduce rows [row0, row0+1024) of x over N.
// One block per row, 256 threads x 4 front-batched float4 (R2-proven shape).
// ---------------------------------------------------------------------------
__global__ __launch_bounds__(256) void k_rowsum(const float* __restrict__ x,
                                                int row0) {
    const int row = row0 + blockIdx.x;
    const float4* __restrict__ p =
        reinterpret_cast<const float4*>(x + (size_t)row * NN);
    const int t = threadIdx.x;

    float4 v0 = p[t];
    float4 v1 = p[t + 256];
    float4 v2 = p[t + 512];
    float4 v3 = p[t + 768];

    float s0 = (v0.x + v0.y) + (v0.z + v0.w);
    float s1 = (v1.x + v1.y) + (v1.z + v1.w);
    float s2 = (v2.x + v2.y) + (v2.z + v2.w);
    float s3 = (v3.x + v3.y) + (v3.z + v3.w);
    float s  = (s0 + s1) + (s2 + s3);

    #pragma unroll
    for (int off = 16; off > 0; off >>= 1)
        s += __shfl_down_sync(0xffffffffu, s, off);

    __shared__ float sm[8];
    if ((t & 31) == 0) sm[t >> 5] = s;
    __syncthreads();
    if (t < 8) {
        float u = sm[t];
        #pragma unroll
        for (int off = 4; off > 0; off >>= 1)
            u += __shfl_down_sync(0xffu, u, off);
        if (t == 0) g_X[row] = u;
    }
}

// ---------------------------------------------------------------------------
// Kernel 2 (half-range): one output row per block (R7-proven shape).
// Every warp redundantly computes the L2-hot 512-dot -> no __syncthreads,
// 8 independent store streams per block.
// ---------------------------------------------------------------------------
__global__ __launch_bounds__(256) void k_out(const float* __restrict__ W1,
                                             float* __restrict__ out,
                                             int bo0) {
    const int bo   = bo0 + blockIdx.x;  // output row
    const int b    = bo >> 8;           // OUT = 256
    const int o    = bo & 255;
    const int warp = threadIdx.x >> 5;  // 0..7
    const int lane = threadIdx.x & 31;

    const float4* __restrict__ wr =
        reinterpret_cast<const float4*>(W1) + (size_t)o * (CIN / 4);
    const float4* __restrict__ xr =
        reinterpret_cast<const float4*>(g_X) + (size_t)b * (CIN / 4);

    float4 a0 = wr[lane];       float4 a1 = wr[lane + 32];
    float4 a2 = wr[lane + 64];  float4 a3 = wr[lane + 96];
    float4 b0 = xr[lane];       float4 b1 = xr[lane + 32];
    float4 b2 = xr[lane + 64];  float4 b3 = xr[lane + 96];

    float s0 = fmaf(a0.x, b0.x, fmaf(a0.y, b0.y, fmaf(a0.z, b0.z, a0.w * b0.w)));
    float s1 = fmaf(a1.x, b1.x, fmaf(a1.y, b1.y, fmaf(a1.z, b1.z, a1.w * b1.w)));
    float s2 = fmaf(a2.x, b2.x, fmaf(a2.y, b2.y, fmaf(a2.z, b2.z, a2.w * b2.w)));
    float s3 = fmaf(a3.x, b3.x, fmaf(a3.y, b3.y, fmaf(a3.z, b3.z, a3.w * b3.w)));
    float s  = (s0 + s1) + (s2 + s3);

    #pragma unroll
    for (int off = 16; off > 0; off >>= 1)     // butterfly: all lanes get sum
        s += __shfl_xor_sync(0xffffffffu, s, off);

    const float  e  = (s > 0.f) ? s : expm1f(s);   // elu, alpha=1
    const float4 v4 = make_float4(e, e, e, e);

    float4* __restrict__ q =
        reinterpret_cast<float4*>(out) + (size_t)bo * (NN / 4) + warp * 128;
    q[lane]      = v4;
    q[lane + 32] = v4;
    q[lane + 64] = v4;
    q[lane + 96] = v4;
}

extern "C" void kernel_launch(void* const* d_in, const int* in_sizes, int n_in,
                              void* d_out, int out_size) {
    const float* x  = (const float*)d_in[0];   // [B, CIN, 1, NN]
    const float* W1 = (const float*)d_in[1];   // [OUT, CIN]
    // d_in[2] = w2, d_in[3] = bias_mat: unused (softmax over size-1 axis == 1)
    float* out = (float*)d_out;                // [B, OUT, 1, NN]

    // One-time plumbing (created on the uncaptured correctness call; inert
    // thereafter). Work per call is identical every call.
    static cudaStream_t s1 = nullptr;
    static cudaEvent_t  evFork = nullptr, evJoin = nullptr;
    if (s1 == nullptr) {
        cudaStreamCreateWithFlags(&s1, cudaStreamNonBlocking);
        cudaEventCreateWithFlags(&evFork, cudaEventDisableTiming);
        cudaEventCreateWithFlags(&evJoin, cudaEventDisableTiming);
    }

    // Fork: side stream joins the capture dependency chain.
    cudaEventRecord(evFork, 0);
    cudaStreamWaitEvent(s1, evFork, 0);

    // Chain A (batches 0,1) on the main stream.
    k_rowsum<<<1024, 256, 0, 0>>>(x, 0);
    k_out  <<< 512, 256, 0, 0>>>(W1, out, 0);

    // Chain B (batches 2,3) on the side stream — fully independent data.
    k_rowsum<<<1024, 256, 0, s1>>>(x, 1024);
    k_out  <<< 512, 256, 0, s1>>>(W1, out, 512);

    // Join: main stream waits for chain B.
    cudaEventRecord(evJoin, s1);
    cudaStreamWaitEvent(0, evJoin, 0);
}